// round 2
// baseline (speedup 1.0000x reference)
#include <cuda_runtime.h>

#define En 4096
#define Bn 8
#define HEADS 32
#define Dh 128

typedef unsigned long long u64;

// Scratch: qkv[3][8][4096], o[8][4096]
__device__ float g_qkv[3 * Bn * En];
__device__ float g_o[Bn * En];

// Packed fp32x2 FMA (Blackwell): d = a*b + d on both 32-bit halves.
__device__ __forceinline__ void fma2(u64 &d, long long a, long long b) {
    asm("fma.rn.f32x2 %0, %1, %2, %0;" : "+l"(d) : "l"((u64)a), "l"((u64)b));
}
__device__ __forceinline__ float2 unpack2(u64 v) {
    float2 r;
    asm("mov.b64 {%0,%1}, %2;" : "=f"(r.x), "=f"(r.y) : "l"(v));
    return r;
}

// Warp computes out[b][row0+r] = sum_e W[row0+r][e] * X[b][e], r=0..1, b=0..7.
// Even/odd e accumulate in the two halves of a packed f32x2 accumulator.
__device__ __forceinline__ void gemm_warp2(const float* __restrict__ W,
                                           const float* __restrict__ X,
                                           float* __restrict__ out,
                                           int row0, int lane) {
    const longlong2* __restrict__ Wv = reinterpret_cast<const longlong2*>(W);
    const longlong2* __restrict__ Xv = reinterpret_cast<const longlong2*>(X);
    // one longlong2 = 4 floats; a 4096-float row = 1024 longlong2

    u64 acc[16];  // [row][batch], packed (even-e, odd-e)
#pragma unroll
    for (int i = 0; i < 16; ++i) acc[i] = 0ull;

#pragma unroll 2
    for (int it = 0; it < 32; ++it) {
        int f4 = it * 32 + lane;
        longlong2 w0 = __ldcs(Wv + (size_t)(row0 + 0) * 1024 + f4);
        longlong2 w1 = __ldcs(Wv + (size_t)(row0 + 1) * 1024 + f4);
#pragma unroll
        for (int g = 0; g < 2; ++g) {
            longlong2 x0 = __ldg(Xv + (g * 4 + 0) * 1024 + f4);
            longlong2 x1 = __ldg(Xv + (g * 4 + 1) * 1024 + f4);
            longlong2 x2 = __ldg(Xv + (g * 4 + 2) * 1024 + f4);
            longlong2 x3 = __ldg(Xv + (g * 4 + 3) * 1024 + f4);
            int c = g * 4;
            // row 0, first element-pair
            fma2(acc[0 + c + 0], w0.x, x0.x);
            fma2(acc[0 + c + 1], w0.x, x1.x);
            fma2(acc[0 + c + 2], w0.x, x2.x);
            fma2(acc[0 + c + 3], w0.x, x3.x);
            // row 1, first element-pair
            fma2(acc[8 + c + 0], w1.x, x0.x);
            fma2(acc[8 + c + 1], w1.x, x1.x);
            fma2(acc[8 + c + 2], w1.x, x2.x);
            fma2(acc[8 + c + 3], w1.x, x3.x);
            // row 0, second element-pair
            fma2(acc[0 + c + 0], w0.y, x0.y);
            fma2(acc[0 + c + 1], w0.y, x1.y);
            fma2(acc[0 + c + 2], w0.y, x2.y);
            fma2(acc[0 + c + 3], w0.y, x3.y);
            // row 1, second element-pair
            fma2(acc[8 + c + 0], w1.y, x0.y);
            fma2(acc[8 + c + 1], w1.y, x1.y);
            fma2(acc[8 + c + 2], w1.y, x2.y);
            fma2(acc[8 + c + 3], w1.y, x3.y);
        }
    }

    // Collapse packed halves, then butterfly transpose-reduce (16 values, 32 lanes).
    float vals[16];
#pragma unroll
    for (int i = 0; i < 16; ++i) {
        float2 p = unpack2(acc[i]);
        vals[i] = p.x + p.y;
    }

    int n = 16;
#pragma unroll
    for (int m = 1; m <= 8; m <<= 1) {
        n >>= 1;
        bool up = (lane & m) != 0;
#pragma unroll
        for (int i = 0; i < n; ++i) {
            float keep = up ? vals[i + n] : vals[i];
            float send = up ? vals[i] : vals[i + n];
            keep += __shfl_xor_sync(0xffffffffu, send, m);
            vals[i] = keep;
        }
    }
    vals[0] += __shfl_xor_sync(0xffffffffu, vals[0], 16);

    if (lane < 16) {
        // value index j: bit3=lane0, bit2=lane1, bit1=lane2, bit0=lane3
        int j = ((lane & 1) << 3) | ((lane & 2) << 1) | ((lane >> 1) & 2) | ((lane >> 3) & 1);
        int r = j >> 3;
        int b = j & 7;
        out[b * En + row0 + r] = vals[0];
    }
}

// grid (256, 3), block 256: blockIdx.y selects projection; 8 warps x 2 rows = 16 rows/block
__global__ void __launch_bounds__(256, 3)
qkv_kernel(const float* __restrict__ Wq, const float* __restrict__ Wk,
           const float* __restrict__ Wv, const float* __restrict__ x) {
    int warp = threadIdx.x >> 5;
    int lane = threadIdx.x & 31;
    int row0 = (blockIdx.x * 8 + warp) * 2;
    const float* W = (blockIdx.y == 0) ? Wq : ((blockIdx.y == 1) ? Wk : Wv);
    gemm_warp2(W, x, g_qkv + blockIdx.y * (Bn * En), row0, lane);
}

// Attention with all-ones KV cache collapses to o[d] = c1 + c2 * v[d] per (b,h).
__global__ void __launch_bounds__(256)
attn_kernel() {
    int gtid = blockIdx.x * blockDim.x + threadIdx.x;
    int warp = gtid >> 5;   // 0..255
    int lane = gtid & 31;
    int b = warp >> 5;      // 0..7
    int h = warp & 31;      // 0..31

    const float4* q4 = reinterpret_cast<const float4*>(g_qkv + (0 * Bn + b) * En + h * Dh);
    const float4* k4 = reinterpret_cast<const float4*>(g_qkv + (1 * Bn + b) * En + h * Dh);
    const float4* v4 = reinterpret_cast<const float4*>(g_qkv + (2 * Bn + b) * En + h * Dh);

    float4 qv = q4[lane];
    float4 kv = k4[lane];
    float4 vv = v4[lane];

    float sq = qv.x + qv.y + qv.z + qv.w;
    float dp = qv.x * kv.x + qv.y * kv.y + qv.z * kv.z + qv.w * kv.w;
#pragma unroll
    for (int m = 16; m >= 1; m >>= 1) {
        sq += __shfl_xor_sync(0xffffffffu, sq, m);
        dp += __shfl_xor_sync(0xffffffffu, dp, m);
    }

    const float scale = 0.08838834764831845f;  // 1/sqrt(128)
    float s0 = sq * scale;                      // score vs every all-ones cache row
    float sL = dp * scale;                      // score vs appended k
    float mx = fmaxf(s0, sL);
    float e0 = expf(s0 - mx);
    float eL = expf(sL - mx);
    float inv = 1.0f / (4095.0f * e0 + eL);
    float c1 = 4095.0f * e0 * inv;              // total weight on ones-vectors
    float c2 = eL * inv;                        // weight on appended v

    float4* o4 = reinterpret_cast<float4*>(g_o + b * En + h * Dh);
    o4[lane] = make_float4(c1 + c2 * vv.x, c1 + c2 * vv.y,
                           c1 + c2 * vv.z, c1 + c2 * vv.w);
}

// grid 256, block 256: out[b][e] = sum_f o[b][f] * Wo[e][f]
__global__ void __launch_bounds__(256, 3)
oproj_kernel(const float* __restrict__ Wo, float* __restrict__ out) {
    int warp = threadIdx.x >> 5;
    int lane = threadIdx.x & 31;
    int row0 = (blockIdx.x * 8 + warp) * 2;
    gemm_warp2(Wo, g_o, out, row0, lane);
}

extern "C" void kernel_launch(void* const* d_in, const int* in_sizes, int n_in,
                              void* d_out, int out_size) {
    const float* x  = (const float*)d_in[0];
    const float* Wq = (const float*)d_in[1];
    const float* Wk = (const float*)d_in[2];
    const float* Wv = (const float*)d_in[3];
    const float* Wo = (const float*)d_in[4];
    float* out = (float*)d_out;

    dim3 gq(256, 3);
    qkv_kernel<<<gq, 256>>>(Wq, Wk, Wv, x);
    attn_kernel<<<32, 256>>>();
    oproj_kernel<<<256, 256>>>(Wo, out);
}

// round 3
// speedup vs baseline: 1.2386x; 1.2386x over previous
#include <cuda_runtime.h>
#include <cstdint>

#define En 4096
#define Bn 8
#define HEADS 32
#define Dh 128
#define CK 128            // k-floats per pipeline chunk
#define NC (En / CK)      // 32 chunks
#define RB 16             // W rows per block
#define SN 3              // pipeline stages

typedef unsigned long long u64;

__device__ __align__(16) float g_qkv[3 * Bn * En];
__device__ __align__(16) float g_o[Bn * En];

__device__ __forceinline__ void fma2(u64 &d, u64 a, u64 b) {
    asm("fma.rn.f32x2 %0, %1, %2, %0;" : "+l"(d) : "l"(a), "l"(b));
}
__device__ __forceinline__ float2 unpack2(u64 v) {
    float2 r;
    asm("mov.b64 {%0,%1}, %2;" : "=f"(r.x), "=f"(r.y) : "l"(v));
    return r;
}
__device__ __forceinline__ void cp16(uint32_t saddr, const float* g) {
    asm volatile("cp.async.cg.shared.global [%0], [%1], 16;" :: "r"(saddr), "l"(g));
}

struct SmemTiles {
    float w[SN][RB][CK];  // 3 * 8KB
    float x[SN][Bn][CK];  // 3 * 4KB
};                        // 36KB total

// Block (128 thr, 4 warps) computes out[b][row0+r] for 16 rows x 8 batches,
// reducing over all 4096 k via a 3-stage cp.async pipeline.
__device__ __forceinline__ void gemm_block16(const float* __restrict__ W,
                                             const float* __restrict__ X,
                                             float* __restrict__ out,
                                             int row0) {
    __shared__ SmemTiles sm;
    const int t = threadIdx.x;
    const int warp = t >> 5, lane = t & 31;

    uint32_t sw_base = (uint32_t)__cvta_generic_to_shared(&sm.w[0][0][0]);
    uint32_t sx_base = (uint32_t)__cvta_generic_to_shared(&sm.x[0][0][0]);

    // stage issue: W = 512 x 16B units, x = 256 x 16B units, 128 threads
    auto issue_stage = [&](int st, int kc) {
        uint32_t sw = sw_base + st * (RB * CK * 4);
        uint32_t sx = sx_base + st * (Bn * CK * 4);
#pragma unroll
        for (int p = 0; p < 4; ++p) {
            int u = p * 128 + t;
            int r = u >> 5, c = u & 31;
            cp16(sw + u * 16, W + (size_t)(row0 + r) * En + kc * CK + c * 4);
        }
#pragma unroll
        for (int p = 0; p < 2; ++p) {
            int u = p * 128 + t;
            int b = u >> 5, c = u & 31;
            cp16(sx + u * 16, X + (size_t)b * En + kc * CK + c * 4);
        }
        asm volatile("cp.async.commit_group;");
    };

    // prologue: stages 0..SN-2
#pragma unroll
    for (int s = 0; s < SN - 1; ++s) issue_stage(s, s);

    u64 acc[32];  // [r(4)][b(8)] packed (even-k, odd-k)
#pragma unroll
    for (int i = 0; i < 32; ++i) acc[i] = 0ull;

    for (int i = 0; i < NC; ++i) {
        asm volatile("cp.async.wait_group %0;" :: "n"(SN - 2));
        __syncthreads();

        int nk = i + SN - 1;
        if (nk < NC) issue_stage(nk % SN, nk);
        else asm volatile("cp.async.commit_group;");

        int st = i % SN;
        longlong2 wv[4];
#pragma unroll
        for (int r = 0; r < 4; ++r)
            wv[r] = *reinterpret_cast<const longlong2*>(&sm.w[st][warp * 4 + r][lane * 4]);
#pragma unroll
        for (int b = 0; b < 8; ++b) {
            longlong2 xv = *reinterpret_cast<const longlong2*>(&sm.x[st][b][lane * 4]);
#pragma unroll
            for (int r = 0; r < 4; ++r) {
                fma2(acc[r * 8 + b], (u64)wv[r].x, (u64)xv.x);
                fma2(acc[r * 8 + b], (u64)wv[r].y, (u64)xv.y);
            }
        }
    }

    // collapse packed halves
    float vals[32];
#pragma unroll
    for (int i = 0; i < 32; ++i) {
        float2 p = unpack2(acc[i]);
        vals[i] = p.x + p.y;
    }

    // butterfly transpose-reduce: 31 shfl+add, lane L ends with value bitrev5(L)
    int n = 32;
#pragma unroll
    for (int m = 1; m <= 16; m <<= 1) {
        n >>= 1;
        bool up = (lane & m) != 0;
#pragma unroll
        for (int i = 0; i < n; ++i) {
            float keep = up ? vals[i + n] : vals[i];
            float send = up ? vals[i] : vals[i + n];
            keep += __shfl_xor_sync(0xffffffffu, send, m);
            vals[i] = keep;
        }
    }
    int j = ((lane & 1) << 4) | ((lane & 2) << 2) | (lane & 4) |
            ((lane >> 2) & 2) | ((lane >> 4) & 1);
    int r = j >> 3;
    int b = j & 7;
    out[(size_t)b * En + row0 + warp * 4 + r] = vals[0];
}

// grid (256, 3), block 128
__global__ void __launch_bounds__(128, 4)
qkv_kernel(const float* __restrict__ Wq, const float* __restrict__ Wk,
           const float* __restrict__ Wv, const float* __restrict__ x) {
    const float* W = (blockIdx.y == 0) ? Wq : ((blockIdx.y == 1) ? Wk : Wv);
    gemm_block16(W, x, g_qkv + blockIdx.y * (Bn * En), blockIdx.x * RB);
}

// Attention with all-ones KV cache collapses to o[d] = c1 + c2 * v[d] per (b,h).
__global__ void __launch_bounds__(256)
attn_kernel() {
    int gtid = blockIdx.x * blockDim.x + threadIdx.x;
    int warp = gtid >> 5;   // 0..255
    int lane = gtid & 31;
    int b = warp >> 5;      // 0..7
    int h = warp & 31;      // 0..31

    const float4* q4 = reinterpret_cast<const float4*>(g_qkv + (0 * Bn + b) * En + h * Dh);
    const float4* k4 = reinterpret_cast<const float4*>(g_qkv + (1 * Bn + b) * En + h * Dh);
    const float4* v4 = reinterpret_cast<const float4*>(g_qkv + (2 * Bn + b) * En + h * Dh);

    float4 qv = q4[lane];
    float4 kv = k4[lane];
    float4 vv = v4[lane];

    float sq = qv.x + qv.y + qv.z + qv.w;
    float dp = qv.x * kv.x + qv.y * kv.y + qv.z * kv.z + qv.w * kv.w;
#pragma unroll
    for (int m = 16; m >= 1; m >>= 1) {
        sq += __shfl_xor_sync(0xffffffffu, sq, m);
        dp += __shfl_xor_sync(0xffffffffu, dp, m);
    }

    const float scale = 0.08838834764831845f;  // 1/sqrt(128)
    float s0 = sq * scale;                      // score vs every all-ones cache row
    float sL = dp * scale;                      // score vs appended k
    float mx = fmaxf(s0, sL);
    float e0 = expf(s0 - mx);
    float eL = expf(sL - mx);
    float inv = 1.0f / (4095.0f * e0 + eL);
    float c1 = 4095.0f * e0 * inv;              // total weight on ones-rows
    float c2 = eL * inv;                        // weight on appended v

    float4* o4 = reinterpret_cast<float4*>(g_o + b * En + h * Dh);
    o4[lane] = make_float4(c1 + c2 * vv.x, c1 + c2 * vv.y,
                           c1 + c2 * vv.z, c1 + c2 * vv.w);
}

// grid 256, block 128
__global__ void __launch_bounds__(128, 4)
oproj_kernel(const float* __restrict__ Wo, float* __restrict__ out) {
    gemm_block16(Wo, g_o, out, blockIdx.x * RB);
}

extern "C" void kernel_launch(void* const* d_in, const int* in_sizes, int n_in,
                              void* d_out, int out_size) {
    const float* x  = (const float*)d_in[0];
    const float* Wq = (const float*)d_in[1];
    const float* Wk = (const float*)d_in[2];
    const float* Wv = (const float*)d_in[3];
    const float* Wo = (const float*)d_in[4];
    float* out = (float*)d_out;

    dim3 gq(256, 3);
    qkv_kernel<<<gq, 128>>>(Wq, Wk, Wv, x);
    attn_kernel<<<32, 256>>>();
    oproj_kernel<<<256, 128>>>(Wo, out);
}